// round 17
// baseline (speedup 1.0000x reference)
#include <cuda_runtime.h>
#include <cuda_fp16.h>
#include <stdint.h>
#include <math.h>

#define B_  2
#define S_  2048
#define D_  1024
#define H_  16
#define DH_ 64
#define M_  (B_*S_)   /* 4096 */

// ---- scratch (static device allocations; no cudaMalloc allowed) ----
__device__ __align__(16) float g_g [M_*D_];

// fp16 attention operands (q/k written by GEMM, rotated in place by rope)
__device__ __align__(16) __half g_qf[M_*D_], g_kf[M_*D_], g_vf[M_*D_];

// fp16 operands for the GEMMs (all single-pass: A-hi @ B-hi)
__device__ __align__(16) __half g_xh [M_*D_];
__device__ __align__(16) __half g_ao [M_*D_];
__device__ __align__(16) __half g_wqh[D_*D_];
__device__ __align__(16) __half g_wkh[D_*D_];
__device__ __align__(16) __half g_wvh[D_*D_];
__device__ __align__(16) __half g_wgh[D_*D_];
__device__ __align__(16) __half g_woh[D_*D_];

// ============================================================================
// PTX helpers
// ============================================================================
__device__ __forceinline__ uint32_t smem_u32(const void* p)
{
    uint32_t a;
    asm("{ .reg .u64 t; cvta.to.shared.u64 t, %1; cvt.u32.u64 %0, t; }"
        : "=r"(a) : "l"(p));
    return a;
}

__device__ __forceinline__ void cp16(uint32_t s, const void* g)
{
    asm volatile("cp.async.cg.shared.global [%0], [%1], 16;" :: "r"(s), "l"(g));
}
#define CP_COMMIT() asm volatile("cp.async.commit_group;" ::: "memory")
template<int N> __device__ __forceinline__ void cp_wait()
{
    asm volatile("cp.async.wait_group %0;" :: "n"(N) : "memory");
}

#define LDSM4(r, addr) \
    asm volatile("ldmatrix.sync.aligned.m8n8.x4.shared.b16 {%0,%1,%2,%3}, [%4];" \
        : "=r"((r)[0]), "=r"((r)[1]), "=r"((r)[2]), "=r"((r)[3]) : "r"(addr))

#define LDSM4T(r, addr) \
    asm volatile("ldmatrix.sync.aligned.m8n8.x4.trans.shared.b16 {%0,%1,%2,%3}, [%4];" \
        : "=r"((r)[0]), "=r"((r)[1]), "=r"((r)[2]), "=r"((r)[3]) : "r"(addr))

__device__ __forceinline__ void mma_f16(float c[4], const uint32_t a[4],
                                        uint32_t b0, uint32_t b1)
{
    asm volatile(
        "mma.sync.aligned.m16n8k16.row.col.f32.f16.f16.f32 "
        "{%0,%1,%2,%3},{%4,%5,%6,%7},{%8,%9},{%0,%1,%2,%3};"
        : "+f"(c[0]), "+f"(c[1]), "+f"(c[2]), "+f"(c[3])
        : "r"(a[0]), "r"(a[1]), "r"(a[2]), "r"(a[3]), "r"(b0), "r"(b1));
}

__device__ __forceinline__ uint32_t packh2(float a, float b)
{
    __half2 h = __floats2half2_rn(a, b);
    return *(uint32_t*)&h;
}

// ============================================================================
// fp16 convert kernel: x + weights -> fp16, exact flattened grid
// ============================================================================
#define XCH   (M_*D_/4)          /* 1048576 */
#define WCH   (D_*D_/4)          /* 262144  */
#define SPLIT_BLOCKS ((XCH + 5*WCH) / 256)   /* 9216 */

__global__ void split_kernel(const float* __restrict__ x,
                             const float* __restrict__ wq, const float* __restrict__ wk,
                             const float* __restrict__ wv, const float* __restrict__ wg,
                             const float* __restrict__ wo)
{
    int gi = blockIdx.x * 256 + threadIdx.x;
    const float* src;
    __half* dh;
    int off;
    if (gi < XCH) {
        src = x; dh = g_xh; off = gi;
    } else {
        int r = gi - XCH;
        int wsel = r >> 18;          // / WCH
        off = r & (WCH - 1);
        switch (wsel) {
            case 0:  src = wq; dh = g_wqh; break;
            case 1:  src = wk; dh = g_wkh; break;
            case 2:  src = wv; dh = g_wvh; break;
            case 3:  src = wg; dh = g_wgh; break;
            default: src = wo; dh = g_woh; break;
        }
    }
    float4 v = ((const float4*)src)[off];
    ((uint2*)dh)[off] = make_uint2(packh2(v.x, v.y), packh2(v.z, v.w));
}

// ============================================================================
// fp16 single-pass GEMM: C = Ah @ Bh^T, fp32 accumulate.
// CTA tile 128x256, 512 threads (16 warps 4x4), warp tile 32x64.
// BK=32, 4-stage cp.async; stage = A(8K)|B(16K) = 24 KB; 96 KB total.
// mma:LDSM = 32:12 per BK-iter (vs 16:16 before). 1 CTA/SM, 4 warps/SMSP.
// OM=0: float C.  OM=1: fp16 C.
// ============================================================================
#define BKH     32
#define NITG    (D_/BKH)
#define A_TILE  (128*BKH*2)           /* 8192 B */
#define B_TILE  (256*BKH*2)           /* 16384 B */
#define STAGE_B (A_TILE + B_TILE)     /* 24576 B */
#define GEMM_SMEM (4*STAGE_B)         /* 98304 B */

struct GemmSrcs { const __half *ah, *bh; };

__device__ __forceinline__ void issue_stage(uint32_t sb, int stage, int k0,
                                            const GemmSrcs& s, int tid)
{
    const uint32_t stg = sb + stage * STAGE_B;
    // A: 128 rows x 64B = 512 cp16 (1/thread)
    {
        int row = tid >> 2;
        int c   = tid & 3;
        int csw = c ^ ((row >> 1) & 3);
        cp16(stg + row * 64 + csw * 16, s.ah + k0 + (size_t)row * D_ + c * 8);
    }
    // B: 256 rows x 64B = 1024 cp16 (2/thread)
    #pragma unroll
    for (int i = 0; i < 2; i++) {
        int j   = tid + i * 512;
        int row = j >> 2;
        int c   = j & 3;
        int csw = c ^ ((row >> 1) & 3);
        cp16(stg + A_TILE + row * 64 + csw * 16, s.bh + k0 + (size_t)row * D_ + c * 8);
    }
}

template<int OM>
__device__ __forceinline__ void gemm_f16_body(const GemmSrcs& s, float* C,
                                              __half* Cf)
{
    extern __shared__ char dsm[];
    const uint32_t sb = smem_u32(dsm);
    const int tid  = threadIdx.x;
    const int lane = tid & 31;
    const int w    = tid >> 5;
    const int wm   = (w & 3) * 32;     // 4 warp-rows of 32
    const int wn   = (w >> 2) * 64;    // 4 warp-cols of 64

    const int l7 = lane & 7;
    uint32_t aoff[2], asw[2], boff[4], bsw[4];
    const int akb = (lane >> 4) & 1;
    const int bkb = (lane >> 3) & 1;
    #pragma unroll
    for (int mf = 0; mf < 2; mf++) {
        int row = wm + mf * 16 + l7 + 8 * ((lane >> 3) & 1);
        aoff[mf] = row * 64;
        asw[mf]  = (row >> 1) & 3;
    }
    #pragma unroll
    for (int nfp = 0; nfp < 4; nfp++) {
        int row = wn + nfp * 16 + l7 + 8 * ((lane >> 4) & 1);
        boff[nfp] = row * 64;
        bsw[nfp]  = (row >> 1) & 3;
    }

    float acc[2][8][4];
    #pragma unroll
    for (int i = 0; i < 2; i++)
        #pragma unroll
        for (int j = 0; j < 8; j++)
            #pragma unroll
            for (int r = 0; r < 4; r++) acc[i][j][r] = 0.f;

    // prologue: stages 0..2 (3 committed groups)
    issue_stage(sb, 0, 0, s, tid);       CP_COMMIT();
    issue_stage(sb, 1, BKH, s, tid);     CP_COMMIT();
    issue_stage(sb, 2, 2 * BKH, s, tid); CP_COMMIT();

    for (int it = 0; it < NITG; it++) {
        cp_wait<2>();
        __syncthreads();
        if (it + 3 < NITG)
            issue_stage(sb, (it + 3) % 4, (it + 3) * BKH, s, tid);
        CP_COMMIT();   // one group per iteration (may be empty) keeps wait<2> exact

        const uint32_t stg = sb + (it % 4) * STAGE_B;
        const uint32_t sA = stg;
        const uint32_t sB = stg + A_TILE;

        #pragma unroll
        for (int ks = 0; ks < 2; ks++) {
            uint32_t bh[4][4];
            #pragma unroll
            for (int nfp = 0; nfp < 4; nfp++) {
                uint32_t off = boff[nfp] + ((((uint32_t)(2*ks + bkb)) ^ bsw[nfp]) << 4);
                LDSM4(bh[nfp], sB + off);
            }
            #pragma unroll
            for (int mf = 0; mf < 2; mf++) {
                uint32_t off = aoff[mf] + ((((uint32_t)(2*ks + akb)) ^ asw[mf]) << 4);
                uint32_t ah[4];
                LDSM4(ah, sA + off);
                #pragma unroll
                for (int nf = 0; nf < 8; nf++) {
                    uint32_t b0 = bh[nf >> 1][(nf & 1)*2], b1 = bh[nf >> 1][(nf & 1)*2 + 1];
                    mma_f16(acc[mf][nf], ah, b0, b1);
                }
            }
        }
        // no trailing barrier: rotation distance 4 + next top barrier suffice
    }

    const int rbase = blockIdx.y * 128 + wm + (lane >> 2);
    const int cbase = blockIdx.x * 256 + wn + ((lane & 3) << 1);
    #pragma unroll
    for (int mf = 0; mf < 2; mf++)
        #pragma unroll
        for (int nf = 0; nf < 8; nf++) {
            const size_t i0 = (size_t)(rbase + mf*16) * D_ + cbase + nf*8;
            const size_t i1 = i0 + (size_t)8 * D_;
            if (OM == 0) {
                *(float2*)(C + i0) = make_float2(acc[mf][nf][0], acc[mf][nf][1]);
                *(float2*)(C + i1) = make_float2(acc[mf][nf][2], acc[mf][nf][3]);
            } else {
                *(uint32_t*)&Cf[i0] = packh2(acc[mf][nf][0], acc[mf][nf][1]);
                *(uint32_t*)&Cf[i1] = packh2(acc[mf][nf][2], acc[mf][nf][3]);
            }
        }
}

__global__ __launch_bounds__(512, 1)
void gemm_qkvg_f16()
{
    GemmSrcs s;
    const size_t yoff = (size_t)blockIdx.y * 128 * D_;
    const size_t xoff = (size_t)blockIdx.x * 256 * D_;
    s.ah = g_xh + yoff;
    switch (blockIdx.z) {
        case 0:  s.bh = g_wqh + xoff; gemm_f16_body<1>(s, nullptr, g_qf); break;
        case 1:  s.bh = g_wkh + xoff; gemm_f16_body<1>(s, nullptr, g_kf); break;
        case 2:  s.bh = g_wvh + xoff; gemm_f16_body<1>(s, nullptr, g_vf); break;
        default: s.bh = g_wgh + xoff; gemm_f16_body<0>(s, g_g, nullptr);  break;
    }
}

__global__ __launch_bounds__(512, 1)
void gemm_out_f16(float* __restrict__ C)
{
    GemmSrcs s;
    const size_t yoff = (size_t)blockIdx.y * 128 * D_;
    const size_t xoff = (size_t)blockIdx.x * 256 * D_;
    s.ah = g_ao + yoff;
    s.bh = g_woh + xoff;
    gemm_f16_body<0>(s, C, nullptr);
}

// ============================================================================
// RoPE: rotate q/k fp16 in place
// ============================================================================
__global__ void rope_kernel()
{
    int i = blockIdx.x * blockDim.x + threadIdx.x;
    if (i >= M_ * H_ * 32) return;
    int j  = i & 31;
    int h  = (i >> 5) & (H_ - 1);
    int bs = i >> 9;
    int s  = bs & (S_ - 1);

    float inv = exp2f(-(float)j * 0.41524101186092029f);
    float ang = (float)s * inv;
    float sn, cs;
    sincosf(ang, &sn, &cs);

    int base = bs * D_ + h * DH_ + j;
    float q1 = __half2float(g_qf[base]), q2 = __half2float(g_qf[base + 32]);
    float k1 = __half2float(g_kf[base]), k2 = __half2float(g_kf[base + 32]);
    g_qf[base]      = __float2half_rn(q1 * cs - q2 * sn);
    g_qf[base + 32] = __float2half_rn(q2 * cs + q1 * sn);
    g_kf[base]      = __float2half_rn(k1 * cs - k2 * sn);
    g_kf[base + 32] = __float2half_rn(k2 * cs + k1 * sn);
}

// ============================================================================
// fp16 single-pass flash retention; PAIRED tile loop (unchanged R16).
// smem: Qf 16K | 4 stages x (K 8K | V 8K) = 80 KB. 2 CTAs/SM.
// ============================================================================
#define QT_ 128
#define KT_ 64
#define OFF_QF 0
#define OFF_ST 16384
#define STG_SZ 16384
#define ATTN_SMEM 81920

__device__ __forceinline__ void attn_issue_q(uint32_t sb, const __half* qf, int tid)
{
    #pragma unroll
    for (int i = 0; i < 4; i++) {
        int u   = tid + i * 256;
        int row = u >> 3;
        int c   = u & 7;
        int cs  = c ^ (row & 7);
        cp16(sb + OFF_QF + row * 128 + cs * 16, qf + (size_t)row * D_ + c * 8);
    }
}

__device__ __forceinline__ void attn_issue_kv(uint32_t sb, int stage, int kt,
                                              const __half* kf, const __half* vf,
                                              int tid)
{
    const __half* srcs[2] = { kf + (size_t)(kt * KT_) * D_,
                              vf + (size_t)(kt * KT_) * D_ };
    const uint32_t stg = sb + OFF_ST + stage * STG_SZ;
    #pragma unroll
    for (int m = 0; m < 2; m++) {
        const __half* src = srcs[m];
        const uint32_t tb = stg + m * 8192;
        #pragma unroll
        for (int i = 0; i < 2; i++) {
            int u   = tid + i * 256;
            int row = u >> 3;
            int c   = u & 7;
            int cs  = c ^ (row & 7);
            cp16(tb + row * 128 + cs * 16, src + (size_t)row * D_ + c * 8);
        }
    }
}

__global__ __launch_bounds__(256, 2)
void attn_kernel()
{
    extern __shared__ char dsm[];
    const uint32_t sb = smem_u32(dsm);

    const int idx = blockIdx.x;
    const int qt  = (S_/QT_ - 1) - (idx >> 5);
    const int h   = idx & 15;
    const int b   = (idx >> 4) & 1;

    const int tid  = threadIdx.x;
    const int lane = tid & 31;
    const int w    = tid >> 5;
    const int l7   = lane & 7;

    const float gamma = 1.0f - exp2f(-5.0f - (float)h);
    const float lg    = log2f(gamma);

    const size_t qoff = (size_t)(b * S_ + qt * QT_) * D_ + h * DH_;
    const size_t koff = (size_t)(b * S_) * D_ + h * DH_;
    const int npair = qt + 1;

    attn_issue_q(sb, g_qf + qoff, tid);
    attn_issue_kv(sb, 0, 0, g_kf + koff, g_vf + koff, tid);
    attn_issue_kv(sb, 1, 1, g_kf + koff, g_vf + koff, tid);
    CP_COMMIT();

    const int rl0 = w * 16 + (lane >> 2);
    const float grow0 = 0.125f * exp2f(lg * (float)rl0);
    const float grow1 = 0.125f * exp2f(lg * (float)(rl0 + 8));
    const float ginv  = exp2f(-lg);
    float gc[8];
    #pragma unroll
    for (int p = 0; p < 8; p++)
        gc[p] = exp2f(-lg * (float)(p * 8 + (lane & 3) * 2));

    float oacc[8][4];
    #pragma unroll
    for (int p = 0; p < 8; p++)
        #pragma unroll
        for (int r = 0; r < 4; r++) oacc[p][r] = 0.f;

    const uint32_t arow = (uint32_t)(w * 16 + l7 + 8 * ((lane >> 3) & 1));
    const uint32_t akb  = (lane >> 4) & 1;
    const uint32_t brow = (uint32_t)(l7 + 8 * ((lane >> 4) & 1));
    const uint32_t bkb  = (lane >> 3) & 1;
    const uint32_t vrow = (uint32_t)(l7 + 8 * ((lane >> 3) & 1));
    const uint32_t vnb  = (lane >> 4) & 1;

    for (int p = 0; p < npair; p++) {
        cp_wait<0>();
        __syncthreads();

        if (p + 1 < npair) {
            attn_issue_kv(sb, (2*p + 2) & 3, 2*p + 2, g_kf + koff, g_vf + koff, tid);
            attn_issue_kv(sb, (2*p + 3) & 3, 2*p + 3, g_kf + koff, g_vf + koff, tid);
            CP_COMMIT();
        }

        #pragma unroll
        for (int hh = 0; hh < 2; hh++) {
            const int kt = 2*p + hh;
            const uint32_t stg = sb + OFF_ST + (kt & 3) * STG_SZ;
            const uint32_t sK = stg, sV = stg + 8192;

            float sacc[8][4];
            #pragma unroll
            for (int q = 0; q < 8; q++)
                #pragma unroll
                for (int r = 0; r < 4; r++) sacc[q][r] = 0.f;

            #pragma unroll
            for (int ks = 0; ks < 4; ks++) {
                uint32_t qa = sb + OFF_QF + arow * 128 + (((2*ks + akb) ^ (arow & 7)) << 4);
                uint32_t ah[4];
                LDSM4(ah, qa);
                #pragma unroll
                for (int g = 0; g < 4; g++) {
                    uint32_t br = g * 16 + brow;
                    uint32_t ba = sK + br * 128 + (((2*ks + bkb) ^ (br & 7)) << 4);
                    uint32_t bh[4];
                    LDSM4(bh, ba);
                    mma_f16(sacc[2*g],   ah, bh[0], bh[1]);
                    mma_f16(sacc[2*g+1], ah, bh[2], bh[3]);
                }
            }

            const int   dbase = qt * QT_ - kt * KT_;
            const float f     = exp2f(lg * (float)dbase);
            const float fr0   = f * grow0;
            const float fr1   = f * grow1;
            const bool  edge  = (dbase < KT_);
            uint32_t SA[4][4];
            #pragma unroll
            for (int q = 0; q < 8; q++) {
                const float c0 = gc[q], c1 = gc[q] * ginv;
                float v00 = sacc[q][0] * fr0 * c0;
                float v01 = sacc[q][1] * fr0 * c1;
                float v10 = sacc[q][2] * fr1 * c0;
                float v11 = sacc[q][3] * fr1 * c1;
                if (edge) {
                    const int tl0 = q * 8 + (lane & 3) * 2;
                    const int d00 = dbase + rl0 - tl0;
                    if (d00 < 0)     v00 = 0.f;
                    if (d00 - 1 < 0) v01 = 0.f;
                    if (d00 + 8 < 0) v10 = 0.f;
                    if (d00 + 7 < 0) v11 = 0.f;
                }
                const int j = q >> 1, o = (q & 1) * 2;
                SA[j][o]     = packh2(v00, v01);
                SA[j][o + 1] = packh2(v10, v11);
            }

            #pragma unroll
            for (int j = 0; j < 4; j++) {
                uint32_t vr = j * 16 + vrow;
                #pragma unroll
                for (int g = 0; g < 4; g++) {
                    uint32_t va = sV + vr * 128 + (((2*g + vnb) ^ (vr & 7)) << 4);
                    uint32_t bv[4];
                    LDSM4T(bv, va);
                    mma_f16(oacc[2*g],   SA[j], bv[0], bv[1]);
                    mma_f16(oacc[2*g+1], SA[j], bv[2], bv[3]);
                }
            }
        }
    }

    // ---- epilogue: y = O * silu(g) -> single fp16 for the out-projection
    const size_t row0 = (size_t)(b * S_ + qt * QT_ + rl0);
    #pragma unroll
    for (int p = 0; p < 8; p++) {
        const int col = h * DH_ + p * 8 + (lane & 3) * 2;
        #pragma unroll
        for (int half = 0; half < 2; half++) {
            const size_t idx2 = (row0 + half * 8) * D_ + col;
            float2 gv = *(const float2*)(g_g + idx2);
            float s0 = gv.x / (1.f + expf(-gv.x));
            float s1 = gv.y / (1.f + expf(-gv.y));
            float y0 = oacc[p][half*2 + 0] * s0;
            float y1 = oacc[p][half*2 + 1] * s1;
            *(uint32_t*)&g_ao[idx2] = packh2(y0, y1);
        }
    }
}

// ============================================================================
extern "C" void kernel_launch(void* const* d_in, const int* in_sizes, int n_in,
                              void* d_out, int out_size)
{
    const float* x  = (const float*)d_in[0];
    const float* wq = (const float*)d_in[1];
    const float* wk = (const float*)d_in[2];
    const float* wv = (const float*)d_in[3];
    const float* wg = (const float*)d_in[4];
    const float* wo = (const float*)d_in[5];
    float* out = (float*)d_out;

    cudaFuncSetAttribute(gemm_qkvg_f16,
                         cudaFuncAttributeMaxDynamicSharedMemorySize, GEMM_SMEM);
    cudaFuncSetAttribute(gemm_out_f16,
                         cudaFuncAttributeMaxDynamicSharedMemorySize, GEMM_SMEM);
    cudaFuncSetAttribute(attn_kernel,
                         cudaFuncAttributeMaxDynamicSharedMemorySize, ATTN_SMEM);

    split_kernel<<<SPLIT_BLOCKS, 256>>>(x, wq, wk, wv, wg, wo);

    gemm_qkvg_f16<<<dim3(D_/256, M_/128, 4), 512, GEMM_SMEM>>>();

    int nrope = M_ * H_ * 32;
    rope_kernel<<<(nrope + 255) / 256, 256>>>();

    attn_kernel<<<(S_/QT_) * H_ * B_, 256, ATTN_SMEM>>>();

    gemm_out_f16<<<dim3(D_/256, M_/128), 512, GEMM_SMEM>>>(out);
}